// round 12
// baseline (speedup 1.0000x reference)
#include <cuda_runtime.h>
#include <cuda_fp16.h>
#include <math.h>
#include <stdint.h>

#define Hdim 2048
#define Idim 4096
#define Edim 8
#define Tdim 2048
#define TK   4096   // T * K slots (always exact: every token picks 2 experts)

// ---------------- scratch (static device arrays; no allocations) ----------------
__device__ __half d_tn[(size_t)Tdim * Hdim];  // normalized tokens (fp16)
__device__ __half d_h[(size_t)TK * Idim];     // w * silu(g)*u (fp16, combine weight folded in)
__device__ int    d_rows[TK];
__device__ float  d_wgt[TK];
__device__ int    d_topi[Tdim * 2];
__device__ float  d_topw[Tdim * 2];
__device__ int    d_counts[Edim];
__device__ int    d_cursor[Edim];
__device__ int    d_offsets[Edim + 1];

// ---------------- helpers ----------------
__device__ __forceinline__ float warpsum(float v) {
#pragma unroll
    for (int o = 16; o > 0; o >>= 1) v += __shfl_down_sync(0xFFFFFFFFu, v, o);
    return v;
}
__device__ __forceinline__ uint32_t smem_u32(const void* p) {
    uint32_t a;
    asm("{ .reg .u64 t; cvta.to.shared.u64 t, %1; cvt.u32.u64 %0, t; }" : "=r"(a) : "l"(p));
    return a;
}
__device__ __forceinline__ void cp16(uint32_t dst, const void* src) {
    asm volatile("cp.async.cg.shared.global [%0], [%1], 16;" :: "r"(dst), "l"(src) : "memory");
}
__device__ __forceinline__ unsigned pack2h(float lo, float hi) {
    __half2 h = __floats2half2_rn(lo, hi);   // .x (lo) in low 16 bits
    return *reinterpret_cast<unsigned*>(&h);
}
__device__ __forceinline__ void mma_f16(float c[4], const unsigned a[4],
                                        unsigned b0, unsigned b1) {
    asm volatile(
        "mma.sync.aligned.m16n8k16.row.col.f32.f16.f16.f32 "
        "{%0,%1,%2,%3}, {%4,%5,%6,%7}, {%8,%9}, {%0,%1,%2,%3};"
        : "+f"(c[0]), "+f"(c[1]), "+f"(c[2]), "+f"(c[3])
        : "r"(a[0]), "r"(a[1]), "r"(a[2]), "r"(a[3]), "r"(b0), "r"(b1));
}
__device__ __forceinline__ void ldsm4(unsigned r[4], uint32_t addr) {
    asm volatile("ldmatrix.sync.aligned.m8n8.x4.shared.b16 {%0,%1,%2,%3}, [%4];"
                 : "=r"(r[0]), "=r"(r[1]), "=r"(r[2]), "=r"(r[3]) : "r"(addr));
}

// ---------------- init ----------------
__global__ void init_kernel(float* __restrict__ out) {
    size_t n = (size_t)Tdim * Hdim;
    for (size_t i = (size_t)blockIdx.x * blockDim.x + threadIdx.x; i < n;
         i += (size_t)gridDim.x * blockDim.x)
        out[i] = 0.0f;
    if (blockIdx.x == 0 && threadIdx.x < Edim) {
        d_counts[threadIdx.x] = 0;
        d_cursor[threadIdx.x] = 0;
    }
}

// ---------------- RMSNorm + router + top-2 ----------------
__global__ __launch_bounds__(256) void routing_kernel(const float* __restrict__ x,
                                                      const float* __restrict__ nw,
                                                      const float* __restrict__ rw) {
    int t = blockIdx.x, tid = threadIdx.x, lane = tid & 31, warp = tid >> 5;
    const float* xr = x + (size_t)t * Hdim;
    __shared__ float sred[8];
    __shared__ float slog[8][9];
    __shared__ float s_rms;

    float ss = 0.0f;
    for (int i = tid; i < Hdim; i += 256) { float v = xr[i]; ss += v * v; }
    ss = warpsum(ss);
    if (lane == 0) sred[warp] = ss;
    __syncthreads();
    if (tid == 0) {
        float tot = 0.0f;
        for (int w = 0; w < 8; w++) tot += sred[w];
        s_rms = rsqrtf(tot / (float)Hdim + 1e-6f);
    }
    __syncthreads();
    float rms = s_rms;

    float acc[8];
#pragma unroll
    for (int e = 0; e < 8; e++) acc[e] = 0.0f;
    for (int i = tid; i < Hdim; i += 256) {
        float tv = xr[i] * rms * nw[i];
        d_tn[(size_t)t * Hdim + i] = __float2half_rn(tv);
#pragma unroll
        for (int e = 0; e < 8; e++) acc[e] += tv * rw[i * Edim + e];
    }
#pragma unroll
    for (int e = 0; e < 8; e++) {
        float v = warpsum(acc[e]);
        if (lane == 0) slog[warp][e] = v;
    }
    __syncthreads();
    if (tid == 0) {
        float lg[8];
        for (int e = 0; e < 8; e++) {
            float s = 0.0f;
            for (int w = 0; w < 8; w++) s += slog[w][e];
            lg[e] = s;
        }
        float mx = lg[0];
        for (int e = 1; e < 8; e++) mx = fmaxf(mx, lg[e]);
        float af[8], sum = 0.0f;
        for (int e = 0; e < 8; e++) { af[e] = expf(lg[e] - mx); sum += af[e]; }
        float inv = 1.0f / sum;
        for (int e = 0; e < 8; e++) af[e] *= inv;
        int i1 = 0;
        for (int e = 1; e < 8; e++) if (af[e] > af[i1]) i1 = e;
        int i2 = (i1 == 0) ? 1 : 0;
        for (int e = 0; e < 8; e++) if (e != i1 && af[e] > af[i2]) i2 = e;
        float v1 = af[i1], v2 = af[i2], s2 = v1 + v2;
        d_topi[2 * t] = i1;  d_topi[2 * t + 1] = i2;
        d_topw[2 * t] = v1 / s2;  d_topw[2 * t + 1] = v2 / s2;
        atomicAdd(&d_counts[i1], 1);
        atomicAdd(&d_counts[i2], 1);
    }
}

__global__ void scan_kernel() {
    if (threadIdx.x == 0) {
        int o = 0;
        for (int e = 0; e < Edim; e++) { d_offsets[e] = o; o += d_counts[e]; }
        d_offsets[Edim] = o;
    }
}

__global__ void assign_kernel() {
    int t = blockIdx.x * blockDim.x + threadIdx.x;
    if (t >= Tdim) return;
    for (int k = 0; k < 2; k++) {
        int e = d_topi[2 * t + k];
        int p = d_offsets[e] + atomicAdd(&d_cursor[e], 1);
        d_rows[p] = t;
        d_wgt[p] = d_topw[2 * t + k];
    }
}

// =====================================================================
// Fused gate+up GEMM: CTA tile 128x64, BOTH weight matrices (NMAT=2).
// 8 warps as 2m x 4n; warp tile 64x16 per matrix; acc = 64 fp32 regs.
// A: fp16, 128 rows x 64B, granule-swizzled, ldmatrix.x4 (frags shared by
// both matrices). B: fp32 [k][n], 64 floats/row, pitch 272B, packed to fp16.
// Epilogue: h = w * silu(g) * u  -> d_h fp16 (combine weight folded in).
// =====================================================================

#define BPH2  272
#define BSTG2 8704
#define STG2  (8192 + 2 * BSTG2)        // 25600
#define SMEM_P (4 * STG2 + 1024)        // 103424 -> 2 CTAs/SM

__global__ __launch_bounds__(256, 2) void proj_gemm(const float* __restrict__ Wg,
                                                    const float* __restrict__ Wu) {
    constexpr int NDIM = Idim;
    constexpr int KDIM = Hdim;
    constexpr int NK = KDIM / 32;

    const int e = blockIdx.z;
    const int cnt = d_counts[e];
    const int m0 = blockIdx.x * 128;
    if (m0 >= cnt) return;
    const int base = d_offsets[e];
    const int n0 = blockIdx.y * 64;
    const int valid = cnt - m0;

    extern __shared__ char smem[];
    const uint32_t sb = smem_u32(smem);
    const int tid = threadIdx.x, wid = tid >> 5, lane = tid & 31;
    const int wm = wid & 1, wn = wid >> 1;        // 2m x 4n
    const int qid = lane >> 2, kl = lane & 3;

    int*   tokS = (int*)(smem + 4 * STG2);
    float* wgtS = (float*)(smem + 4 * STG2 + 512);
    if (tid < 128) {
        int slot = base + m0 + min(tid, valid - 1);
        tokS[tid] = d_rows[slot];
        wgtS[tid] = d_wgt[slot];
    }
    __syncthreads();

    // ---- A staging: each thread copies 2 granules (rows r0, r0+64; k-group gA) ----
    const int r0 = tid >> 2, gA = tid & 3;
    const __half* arow0 = d_tn + (size_t)tokS[min(r0, valid - 1)] * KDIM + gA * 8;
    const __half* arow1 = d_tn + (size_t)tokS[min(r0 + 64, valid - 1)] * KDIM + gA * 8;
    const uint32_t swA = (gA ^ ((r0 >> 1) & 3)) * 16;
    const uint32_t adst0 = r0 * 64 + swA;
    const uint32_t adst1 = (r0 + 64) * 64 + swA;

    // ---- B staging: 4 cp16/thread/stage. mat = tid>>7; within the mat's 128
    //      threads: row = t2>>2 (0..31), seg = (t2&3)*4 + j (0..15). Covers all
    //      32 rows x 16 segs x 2 mats = 1024 16B-chunks exactly once. ----
    const int bmat = tid >> 7, t2 = tid & 127;
    const int brow = t2 >> 2, bseg0 = (t2 & 3) * 4;
    const float* bsrc = (bmat ? Wu : Wg) + (size_t)e * KDIM * NDIM +
                        (size_t)brow * NDIM + n0 + bseg0 * 4;
    const uint32_t bdst = bmat * BSTG2 + brow * BPH2 + bseg0 * 16;

    auto load_stage = [&](int kc, int buf) {
        uint32_t ab = sb + buf * STG2;
        const int k0 = kc * 32;
        cp16(ab + adst0, arow0 + k0);
        cp16(ab + adst1, arow1 + k0);
        const float* bs = bsrc + (size_t)k0 * NDIM;
        uint32_t bd = ab + 8192 + bdst;
#pragma unroll
        for (int j = 0; j < 4; j++)
            cp16(bd + j * 16, bs + j * 4);
        asm volatile("cp.async.commit_group;" ::: "memory");
    };

    // ---- ldmatrix per-lane address pieces (identical to proven R7 A-side) ----
    const int t8 = lane >> 3;
    const int gt = t8 >> 1;
    const int rL = (t8 & 1) * 8 + (lane & 7);
    uint32_t r64[4], swm[4];
#pragma unroll
    for (int mf = 0; mf < 4; mf++) {
        int r = wm * 64 + mf * 16 + rL;
        r64[mf] = r * 64;
        swm[mf] = (r >> 1) & 3;
    }

    float accG[4][2][4], accU[4][2][4];
#pragma unroll
    for (int mf = 0; mf < 4; mf++)
#pragma unroll
        for (int nf = 0; nf < 2; nf++)
#pragma unroll
            for (int q = 0; q < 4; q++) { accG[mf][nf][q] = 0.0f; accU[mf][nf][q] = 0.0f; }

    load_stage(0, 0);
    load_stage(1, 1);
    load_stage(2, 2);

#pragma unroll 1
    for (int kc = 0; kc < NK; kc++) {
        if (kc < NK - 2)       asm volatile("cp.async.wait_group 2;" ::: "memory");
        else if (kc == NK - 2) asm volatile("cp.async.wait_group 1;" ::: "memory");
        else                   asm volatile("cp.async.wait_group 0;" ::: "memory");
        __syncthreads();
        if (kc + 3 < NK) load_stage(kc + 3, (kc + 3) & 3);

        const uint32_t Abase = sb + (kc & 3) * STG2;
        const char* Bb = smem + (kc & 3) * STG2 + 8192;
#pragma unroll
        for (int ks16 = 0; ks16 < 2; ks16++) {
            unsigned a[4][4];
#pragma unroll
            for (int mf = 0; mf < 4; mf++)
                ldsm4(a[mf], Abase + r64[mf] + (((ks16 * 2 + gt) ^ swm[mf]) << 4));
            const int ksr = ks16 * 16;
#pragma unroll
            for (int mat = 0; mat < 2; mat++) {
                const char* Bm = Bb + mat * BSTG2;
#pragma unroll
                for (int nf = 0; nf < 2; nf++) {
                    const char* p = Bm + (wn * 16 + nf * 8 + qid) * 4;
                    float b00 = *(const float*)(p + (ksr + 2 * kl) * BPH2);
                    float b01 = *(const float*)(p + (ksr + 2 * kl + 1) * BPH2);
                    float b10 = *(const float*)(p + (ksr + 2 * kl + 8) * BPH2);
                    float b11 = *(const float*)(p + (ksr + 2 * kl + 9) * BPH2);
                    unsigned b0 = pack2h(b00, b01);
                    unsigned b1 = pack2h(b10, b11);
                    float (*acc)[2][4] = mat ? accU : accG;
#pragma unroll
                    for (int mf = 0; mf < 4; mf++)
                        mma_f16(acc[mf][nf], a[mf], b0, b1);
                }
            }
        }
    }

    // ---- epilogue: h = w * silu(g) * u -> d_h fp16 ----
#pragma unroll
    for (int mf = 0; mf < 4; mf++) {
#pragma unroll
        for (int half = 0; half < 2; half++) {
            int r = wm * 64 + mf * 16 + qid + half * 8;
            if (r >= valid) continue;
            float w = wgtS[r];
#pragma unroll
            for (int nf = 0; nf < 2; nf++) {
                int col = n0 + wn * 16 + nf * 8 + kl * 2;
                float g0 = accG[mf][nf][half * 2 + 0];
                float g1 = accG[mf][nf][half * 2 + 1];
                float u0 = accU[mf][nf][half * 2 + 0];
                float u1 = accU[mf][nf][half * 2 + 1];
                float h0 = w * g0 / (1.0f + expf(-g0)) * u0;
                float h1 = w * g1 / (1.0f + expf(-g1)) * u1;
                *(__half2*)(d_h + (size_t)(base + m0 + r) * Idim + col) =
                    __floats2half2_rn(h0, h1);
            }
        }
    }
}

// =====================================================================
// Down GEMM (R7 MODE 1, unchanged shape): CTA 128x128, warp 64x32,
// A = d_h rows (weight pre-folded), atomic scatter into out.
// =====================================================================

#define BPH   528
#define ASTG  8192
#define STG   (ASTG + 32 * BPH)       // 25088
#define SMEM_D (4 * STG + 1024)       // 101376 -> 2 CTAs/SM

__global__ __launch_bounds__(256, 2) void down_gemm(const float* __restrict__ W,
                                                    float* __restrict__ Out) {
    constexpr int NDIM = Hdim;
    constexpr int KDIM = Idim;
    constexpr int NK = KDIM / 32;

    const int e = blockIdx.z;
    const int cnt = d_counts[e];
    const int m0 = blockIdx.x * 128;
    if (m0 >= cnt) return;
    const int base = d_offsets[e];
    const int n0 = blockIdx.y * 128;
    const int valid = cnt - m0;

    extern __shared__ char smem[];
    const uint32_t sb = smem_u32(smem);
    const int tid = threadIdx.x, wid = tid >> 5, lane = tid & 31;
    const int wm = wid & 1, wn = wid >> 1;
    const int qid = lane >> 2, kl = lane & 3;

    int* tokS = (int*)(smem + 4 * STG);
    if (tid < 128) {
        int slot = base + m0 + min(tid, valid - 1);
        tokS[tid] = d_rows[slot];
    }
    __syncthreads();

    const int r0 = tid >> 2, gA = tid & 3;
    const __half* arow0 = d_h + (size_t)(base + m0 + min(r0, valid - 1)) * KDIM + gA * 8;
    const __half* arow1 = d_h + (size_t)(base + m0 + min(r0 + 64, valid - 1)) * KDIM + gA * 8;
    const uint32_t swA = (gA ^ ((r0 >> 1) & 3)) * 16;
    const uint32_t adst0 = r0 * 64 + swA;
    const uint32_t adst1 = (r0 + 64) * 64 + swA;

    const float* Wsrc = W + (size_t)e * KDIM * NDIM + n0 + lane * 4;

    auto load_stage = [&](int kc, int buf) {
        uint32_t ab = sb + buf * STG;
        const int k0 = kc * 32;
        cp16(ab + adst0, arow0 + k0);
        cp16(ab + adst1, arow1 + k0);
        uint32_t bb = ab + ASTG;
#pragma unroll
        for (int j = 0; j < 4; j++) {
            int kk = j * 8 + wid;
            cp16(bb + kk * BPH + lane * 16, Wsrc + (size_t)(k0 + kk) * NDIM);
        }
        asm volatile("cp.async.commit_group;" ::: "memory");
    };

    const int t8 = lane >> 3;
    const int gt = t8 >> 1;
    const int rL = (t8 & 1) * 8 + (lane & 7);
    uint32_t r64[4], swm[4];
#pragma unroll
    for (int mf = 0; mf < 4; mf++) {
        int r = wm * 64 + mf * 16 + rL;
        r64[mf] = r * 64;
        swm[mf] = (r >> 1) & 3;
    }

    float acc[4][4][4];
#pragma unroll
    for (int mf = 0; mf < 4; mf++)
#pragma unroll
        for (int nf = 0; nf < 4; nf++)
#pragma unroll
            for (int q = 0; q < 4; q++) acc[mf][nf][q] = 0.0f;

    load_stage(0, 0);
    load_stage(1, 1);
    load_stage(2, 2);

#pragma unroll 1
    for (int kc = 0; kc < NK; kc++) {
        if (kc < NK - 2)       asm volatile("cp.async.wait_group 2;" ::: "memory");
        else if (kc == NK - 2) asm volatile("cp.async.wait_group 1;" ::: "memory");
        else                   asm volatile("cp.async.wait_group 0;" ::: "memory");
        __syncthreads();
        if (kc + 3 < NK) load_stage(kc + 3, (kc + 3) & 3);

        const uint32_t Abase = sb + (kc & 3) * STG;
        const char* Bb = smem + (kc & 3) * STG + ASTG;
#pragma unroll
        for (int ks16 = 0; ks16 < 2; ks16++) {
            unsigned a[4][4];
#pragma unroll
            for (int mf = 0; mf < 4; mf++)
                ldsm4(a[mf], Abase + r64[mf] + (((ks16 * 2 + gt) ^ swm[mf]) << 4));
            const int ksr = ks16 * 16;
#pragma unroll
            for (int nf = 0; nf < 4; nf++) {
                const char* p = Bb + (wn * 32 + nf * 8 + qid) * 4;
                float b00 = *(const float*)(p + (ksr + 2 * kl) * BPH);
                float b01 = *(const float*)(p + (ksr + 2 * kl + 1) * BPH);
                float b10 = *(const float*)(p + (ksr + 2 * kl + 8) * BPH);
                float b11 = *(const float*)(p + (ksr + 2 * kl + 9) * BPH);
                unsigned b0 = pack2h(b00, b01);
                unsigned b1 = pack2h(b10, b11);
#pragma unroll
                for (int mf = 0; mf < 4; mf++)
                    mma_f16(acc[mf][nf], a[mf], b0, b1);
            }
        }
    }

    // epilogue: bare atomic scatter (combine weight already folded into d_h)
#pragma unroll
    for (int mf = 0; mf < 4; mf++) {
#pragma unroll
        for (int half = 0; half < 2; half++) {
            int r = wm * 64 + mf * 16 + qid + half * 8;
            if (r >= valid) continue;
            int tok = tokS[r];
#pragma unroll
            for (int nf = 0; nf < 4; nf++) {
                int col = n0 + wn * 32 + nf * 8 + kl * 2;
                float* dst = Out + (size_t)tok * Hdim + col;
                atomicAdd(dst + 0, acc[mf][nf][half * 2 + 0]);
                atomicAdd(dst + 1, acc[mf][nf][half * 2 + 1]);
            }
        }
    }
}

// ---------------- launch ----------------
extern "C" void kernel_launch(void* const* d_in, const int* in_sizes, int n_in,
                              void* d_out, int out_size) {
    const float* x  = (const float*)d_in[0];
    const float* nw = (const float*)d_in[1];
    const float* rw = (const float*)d_in[2];
    const float* wg = (const float*)d_in[3];
    const float* wu = (const float*)d_in[4];
    const float* wd = (const float*)d_in[5];
    float* out = (float*)d_out;

    static bool attr_done = false;
    if (!attr_done) {
        cudaFuncSetAttribute(proj_gemm, cudaFuncAttributeMaxDynamicSharedMemorySize, SMEM_P);
        cudaFuncSetAttribute(down_gemm, cudaFuncAttributeMaxDynamicSharedMemorySize, SMEM_D);
        attr_done = true;
    }

    init_kernel<<<512, 256>>>(out);
    routing_kernel<<<Tdim, 256>>>(x, nw, rw);
    scan_kernel<<<1, 32>>>();
    assign_kernel<<<Tdim / 256, 256>>>();

    dim3 g1(TK / 128, Idim / 64, Edim);    // 32 x 64 x 8, most x exit early
    proj_gemm<<<g1, 256, SMEM_P>>>(wg, wu);

    dim3 g2(TK / 128, Hdim / 128, Edim);   // 32 x 16 x 8
    down_gemm<<<g2, 256, SMEM_D>>>(wd, out);
}